// round 1
// baseline (speedup 1.0000x reference)
#include <cuda_runtime.h>
#include <stdint.h>

#define NTHREADS 256

// Packed f32x2 FMA — ptxas never emits FFMA2 from C++; PTX fma.rn.f32x2 is the
// only route (SASS_QUICKREF "Patterns absent from ptxas output").
__device__ __forceinline__ unsigned long long fma2(unsigned long long a,
                                                   unsigned long long b,
                                                   unsigned long long c) {
    unsigned long long d;
    asm("fma.rn.f32x2 %0, %1, %2, %3;" : "=l"(d) : "l"(a), "l"(b), "l"(c));
    return d;
}

// Broadcast a scalar into both halves of an f32x2 register pair.
__device__ __forceinline__ unsigned long long pack2(float x) {
    unsigned long long d;
    asm("mov.b64 %0, {%1, %1};" : "=l"(d) : "f"(x));
    return d;
}

__global__ void __launch_bounds__(NTHREADS, 2)
hermite_kernel(const float* __restrict__ mlp,
               const float* __restrict__ cd,
               const float* __restrict__ sig,
               const float* __restrict__ gw,
               const float* __restrict__ W,
               float* __restrict__ out,
               int total /* B*N */) {
    // P[k][j][8 x ulonglong2] : 6 monomial-basis matrices folded with is2/is4.
    // 32 k * 6 j * 16 f32x2 (o padded 31->32) = 24576 bytes.
    __shared__ ulonglong2 Psh[32][6][8];
    // Epilogue staging: 64 rows x 31 cols, stride 33 -> conflict-free.
    __shared__ float stage[64][33];

    // ---- Build P in SMEM (fold sigmas into rbf_weights) ----
    float* Pf = reinterpret_cast<float*>(Psh);
    for (int i = threadIdx.x; i < 32 * 6 * 32; i += NTHREADS) {
        int o  = i & 31;
        int kj = i >> 5;
        int j  = kj % 6;
        int k  = kj / 6;
        float val = 0.0f;
        if (o < 31) {
            float s   = sig[k];
            float s2  = s * s;
            float is2 = 1.0f / (s2 + 1e-6f);
            float is4 = 1.0f / (s2 * s2 + 1e-6f);
            const float* Wk = W + k * 186 + o;  // [k][h][o], H=6, O=31
            if      (j == 0) val = Wk[0] - is2 * (Wk[93] + Wk[155]);
            else if (j == 1) val = -is2 * Wk[62];   // dx   * (-is2*W[h=2])
            else if (j == 2) val = -is2 * Wk[31];   // dy   * (-is2*W[h=1])
            else if (j == 3) val = is4 * Wk[155];   // dx^2 * ( is4*W[h=5])
            else if (j == 4) val = is4 * Wk[124];   // dxdy * ( is4*W[h=4])
            else             val = is4 * Wk[93];    // dy^2 * ( is4*W[h=3])
        }
        Pf[i] = val;
    }
    __syncthreads();

    int  n     = blockIdx.x * NTHREADS + threadIdx.x;
    bool valid = n < total;

    unsigned long long acc[16];
#pragma unroll
    for (int v = 0; v < 16; v++) acc[v] = 0ull;

    if (valid) {
        // coord_diff row: 64 floats = 256B aligned; gw row: 32 floats = 128B aligned.
        const float4* cd4 = reinterpret_cast<const float4*>(cd) + (size_t)n * 16;
        const float2* gw2 = reinterpret_cast<const float2*>(gw) + (size_t)n * 16;

#pragma unroll 1   // keep body ~<6KB so it stays in L0 I$
        for (int k0 = 0; k0 < 32; k0 += 2) {
            float4 c = cd4[k0 >> 1];  // (dx_k, dy_k, dx_{k+1}, dy_{k+1})
            float2 g = gw2[k0 >> 1];
#pragma unroll
            for (int kk = 0; kk < 2; kk++) {
                float dx = kk ? c.z : c.x;
                float dy = kk ? c.w : c.y;
                float gk = kk ? g.y : g.x;
                int   k  = k0 + kk;

                float m1f = gk * dx, m2f = gk * dy;
                unsigned long long m[6];
                m[0] = pack2(gk);
                m[1] = pack2(m1f);
                m[2] = pack2(m2f);
                m[3] = pack2(m1f * dx);
                m[4] = pack2(m1f * dy);
                m[5] = pack2(m2f * dy);

#pragma unroll
                for (int j = 0; j < 6; j++) {
                    const ulonglong2* pj = Psh[k][j];
                    unsigned long long mj = m[j];
#pragma unroll
                    for (int vv = 0; vv < 8; vv++) {
                        ulonglong2 p = pj[vv];  // LDS.128 broadcast (N=1)
                        acc[2 * vv]     = fma2(mj, p.x, acc[2 * vv]);
                        acc[2 * vv + 1] = fma2(mj, p.y, acc[2 * vv + 1]);
                    }
                }
            }
        }
    }

    // ---- Unpack accumulators ----
    float accf[31];
#pragma unroll
    for (int v = 0; v < 16; v++) {
        unsigned long long a = acc[v];
        float lo = __uint_as_float((unsigned)(a & 0xffffffffu));
        float hi = __uint_as_float((unsigned)(a >> 32));
        if (2 * v < 31)     accf[2 * v]     = lo;
        if (2 * v + 1 < 31) accf[2 * v + 1] = hi;
    }

    // ---- Coalesced epilogue via SMEM staging (4 waves of 64 rows) ----
    // Direct per-thread row I/O of mlp/out (124B rows) would cost 32 L1tex
    // wavefronts per LDG; staging makes all gmem traffic unit-stride.
    int sgrp = threadIdx.x >> 6;
    int r    = threadIdx.x & 63;
    size_t lim = (size_t)total * 31;

    for (int s = 0; s < 4; s++) {
        __syncthreads();
        if (sgrp == s) {
#pragma unroll
            for (int o = 0; o < 31; o++) stage[r][o] = accf[o];
        }
        __syncthreads();
        size_t base = ((size_t)blockIdx.x * NTHREADS + (size_t)s * 64) * 31;
        for (int e = threadIdx.x; e < 64 * 31; e += NTHREADS) {
            size_t gidx = base + e;
            if (gidx < lim) {
                int rr = e / 31;           // strength-reduced to mul-hi by ptxas
                int o  = e - rr * 31;
                out[gidx] = mlp[gidx] * stage[rr][o];
            }
        }
    }
}

extern "C" void kernel_launch(void* const* d_in, const int* in_sizes, int n_in,
                              void* d_out, int out_size) {
    const float* mlp = (const float*)d_in[0];  // [B,N,31]
    const float* cd  = (const float*)d_in[1];  // [B,N,32,2]
    const float* sig = (const float*)d_in[2];  // [32]
    const float* gw  = (const float*)d_in[3];  // [B,N,32]
    const float* W   = (const float*)d_in[4];  // [32,6,31]

    int total  = in_sizes[3] / 32;  // B*N
    int blocks = (total + NTHREADS - 1) / NTHREADS;
    hermite_kernel<<<blocks, NTHREADS>>>(mlp, cd, sig, gw, W, (float*)d_out, total);
}